// round 1
// baseline (speedup 1.0000x reference)
#include <cuda_runtime.h>
#include <math.h>

#define NMAX 65536
#define TWO_PI_F  6.283185307179586f
#define INV_4PI_F 0.07957747154594767f

// ---------------- scratch (__device__ globals; no allocation allowed) ----------------
__device__ float d_W1T[256 * 2048];
__device__ float d_W2T[256 * 256];
__device__ float d_W3T[256 * 256];
__device__ float d_W4T[256 * 256];
__device__ float d_y[(size_t)NMAX * 2048];   // [sin | cos] per point, 512MB
__device__ float d_h[(size_t)4 * NMAX * 256];
__device__ float d_s[(size_t)4 * NMAX * 256];
__device__ float d_g[(size_t)2 * NMAX * 256];
__device__ float d_gy[(size_t)NMAX * 2048];  // dL/dy, 512MB

// ---------------- helpers ----------------
__device__ __forceinline__ unsigned long long fma2(unsigned long long a,
                                                   unsigned long long b,
                                                   unsigned long long c) {
    unsigned long long d;
    asm("fma.rn.f32x2 %0, %1, %2, %3;" : "=l"(d) : "l"(a), "l"(b), "l"(c));
    return d;
}
__device__ __forceinline__ unsigned long long bcast2(float b) {
    unsigned long long bb;
    asm("mov.b64 %0, {%1, %1};" : "=l"(bb) : "r"(__float_as_uint(b)));
    return bb;
}
__device__ __forceinline__ float clip1(float v) { return fminf(fmaxf(v, -1.0f), 1.0f); }

// ---------------- transpose: out[c*R + r] = in[r*C + c] ----------------
__global__ void k_tr(const float* __restrict__ in, float* __restrict__ out, int R, int C) {
    int idx = blockIdx.x * blockDim.x + threadIdx.x;
    if (idx >= R * C) return;
    int r = idx / C, c = idx - r * C;
    out[(size_t)c * R + r] = in[idx];
}

// ---------------- RFF features: y[p][j]=sin(2pi x.B[:,j]), y[p][1024+j]=cos ----------------
__global__ void k_y(const float* __restrict__ x, const float* __restrict__ B,
                    float* __restrict__ y, int n) {
    int idx = blockIdx.x * blockDim.x + threadIdx.x;
    if (idx >= n * 1024) return;
    int p = idx >> 10, j = idx & 1023;
    float x0 = clip1(x[p * 3 + 0]);
    float x1 = clip1(x[p * 3 + 1]);
    float x2 = clip1(x[p * 3 + 2]);
    float proj = TWO_PI_F * (x0 * B[j] + x1 * B[1024 + j] + x2 * B[2048 + j]);
    float sv, cv;
    sincosf(proj, &sv, &cv);
    y[(size_t)p * 2048 + j] = sv;
    y[(size_t)p * 2048 + 1024 + j] = cv;
}

// ---------------- GEMM: C[p,c] = sum_k A[p,k] * Bm[c*ldb+k], p-tile 128, c-tile 64 ----------------
// EPI 0: plain store. EPI 1: z=v+bias[c]; store softplus(z) to C, sigmoid(z) to Cs.
// EPI 2: v *= Sm[p*256+c]; store to C.
#define KC 128
template <int EPI>
__global__ __launch_bounds__(256, 2)
void k_gemm(const float* __restrict__ A, int lda,
            const float* __restrict__ Bm, int ldb,
            const float* __restrict__ bias,
            const float* __restrict__ Sm,
            float* __restrict__ C, float* __restrict__ Cs,
            int ldc, int K, int n) {
    extern __shared__ float sm[];
    float* sA = sm;              // 64 pair-rows x 129 float2 (stride 258 floats)
    float* sB = sm + 64 * 258;   // 64 rows x 129 floats
    const int tid = threadIdx.x;
    const int p0 = blockIdx.x * 128;
    const int c0 = blockIdx.y * 64;
    const int px = tid & 15;     // pair-row group
    const int cx = tid >> 4;     // col group (4 cols each)

    unsigned long long acc[4][4];
#pragma unroll
    for (int i = 0; i < 4; i++)
#pragma unroll
        for (int ii = 0; ii < 4; ii++) acc[i][ii] = 0ull;

    for (int kc = 0; kc < K; kc += KC) {
        // stage A tile: 128 rows x 128 k, packed as pairs (row0,row1) in float2
        {
            const float* Ab = A + (size_t)p0 * lda + kc;
#pragma unroll
            for (int it = 0; it < 16; it++) {
                int lin = tid + 256 * it;       // float4 id, 4096 total
                int row = lin >> 5;             // 0..127
                int kq = (lin & 31) << 2;       // 0..124
                float4 v = make_float4(0.f, 0.f, 0.f, 0.f);
                if (p0 + row < n) v = *(const float4*)(Ab + (size_t)row * lda + kq);
                float* dst = sA + (row >> 1) * 258 + (row & 1);
                dst[(kq + 0) << 1] = v.x;
                dst[(kq + 1) << 1] = v.y;
                dst[(kq + 2) << 1] = v.z;
                dst[(kq + 3) << 1] = v.w;
            }
        }
        // stage B tile: 64 rows x 128 k
        {
            const float* Bb = Bm + (size_t)c0 * ldb + kc;
#pragma unroll
            for (int it = 0; it < 8; it++) {
                int lin = tid + 256 * it;       // 2048 float4
                int row = lin >> 5;             // 0..63
                int kq = (lin & 31) << 2;
                float4 v = *(const float4*)(Bb + (size_t)row * ldb + kq);
                float* dst = sB + row * 129 + kq;
                dst[0] = v.x; dst[1] = v.y; dst[2] = v.z; dst[3] = v.w;
            }
        }
        __syncthreads();

        const float* sAp = sA + px * 258;
        const float* sBc = sB + (cx << 2) * 129;
#pragma unroll 4
        for (int k = 0; k < KC; k++) {
            unsigned long long a[4];
#pragma unroll
            for (int i = 0; i < 4; i++)
                a[i] = *(const unsigned long long*)(sAp + i * (16 * 258) + (k << 1));
#pragma unroll
            for (int ii = 0; ii < 4; ii++) {
                unsigned long long bb = bcast2(sBc[ii * 129 + k]);
#pragma unroll
                for (int i = 0; i < 4; i++) acc[i][ii] = fma2(a[i], bb, acc[i][ii]);
            }
        }
        __syncthreads();
    }

    // epilogue
#pragma unroll
    for (int i = 0; i < 4; i++) {
        int p_base = p0 + (px + 16 * i) * 2;
#pragma unroll
        for (int comp = 0; comp < 2; comp++) {
            int p = p_base + comp;
            if (p >= n) continue;
#pragma unroll
            for (int ii = 0; ii < 4; ii++) {
                int c = c0 + (cx << 2) + ii;
                float2 v2 = *(float2*)&acc[i][ii];
                float v = comp ? v2.y : v2.x;
                if (EPI == 0) {
                    C[(size_t)p * ldc + c] = v;
                } else if (EPI == 1) {
                    float z = v + bias[c];
                    float e = expf(-fabsf(z));
                    float h = fmaxf(z, 0.0f) + log1pf(e);
                    float sg = (z >= 0.0f) ? 1.0f / (1.0f + e) : e / (1.0f + e);
                    C[(size_t)p * 256 + c] = h;
                    Cs[(size_t)p * 256 + c] = sg;
                } else {  // EPI == 2
                    C[(size_t)p * 256 + c] = v * Sm[(size_t)p * 256 + c];
                }
            }
        }
    }
}

// ---------------- head: f = h4 . W5 + b5, g4 = W5 * s4 ----------------
__global__ void k_head(const float* __restrict__ h4, const float* __restrict__ s4,
                       const float* __restrict__ W5, const float* __restrict__ b5,
                       float* __restrict__ out_f, float* __restrict__ g4, int n) {
    __shared__ float sw[256];
    int tid = threadIdx.x;
    sw[tid] = W5[tid];
    __syncthreads();
    int p = blockIdx.x * 8 + (tid >> 5);
    int lane = tid & 31;
    if (p >= n) return;
    float acc = 0.f;
    const float* hr = h4 + (size_t)p * 256;
    const float* sr = s4 + (size_t)p * 256;
    float* gr = g4 + (size_t)p * 256;
#pragma unroll
    for (int i = lane; i < 256; i += 32) {
        float w = sw[i];
        acc += hr[i] * w;
        gr[i] = w * sr[i];
    }
#pragma unroll
    for (int o = 16; o; o >>= 1) acc += __shfl_xor_sync(0xffffffffu, acc, o);
    if (lane == 0) out_f[p] = acc + b5[0];
}

// ---------------- Biot-Savart: thread per point ----------------
__global__ void k_biot(const float* __restrict__ x, const float* __restrict__ bdry,
                       float* __restrict__ out_alpha, int n, int M) {
    __shared__ float bx[512], by[512], bz[512];
    __shared__ float sgx[512], sgy[512], sgz[512];
    __shared__ float smx[512], smy[512], smz[512];
    int tid = threadIdx.x;
    for (int m = tid; m < M; m += blockDim.x) {
        bx[m] = bdry[m * 3 + 0];
        by[m] = bdry[m * 3 + 1];
        bz[m] = bdry[m * 3 + 2];
    }
    __syncthreads();
    for (int m = tid; m < M; m += blockDim.x) {
        int m2 = (m + 1) == M ? 0 : m + 1;
        sgx[m] = bx[m2] - bx[m];
        sgy[m] = by[m2] - by[m];
        sgz[m] = bz[m2] - bz[m];
        smx[m] = 0.5f * (bx[m2] + bx[m]);
        smy[m] = 0.5f * (by[m2] + by[m]);
        smz[m] = 0.5f * (bz[m2] + bz[m]);
    }
    __syncthreads();
    int p = blockIdx.x * blockDim.x + tid;
    if (p >= n) return;
    float x0 = clip1(x[p * 3 + 0]);
    float x1 = clip1(x[p * 3 + 1]);
    float x2 = clip1(x[p * 3 + 2]);
    float ax = 0.f, ay = 0.f, az = 0.f;
    for (int m = 0; m < M; m++) {
        float dx = x0 - smx[m], dy = x1 - smy[m], dz = x2 - smz[m];
        float cxv = sgy[m] * dz - sgz[m] * dy;
        float cyv = sgz[m] * dx - sgx[m] * dz;
        float czv = sgx[m] * dy - sgy[m] * dx;
        float r2 = dx * dx + dy * dy + dz * dz;
        float inv = rsqrtf(r2);
        float w = inv * inv * inv;
        ax += cxv * w; ay += cyv * w; az += czv * w;
    }
    out_alpha[p * 3 + 0] = INV_4PI_F * ax;
    out_alpha[p * 3 + 1] = INV_4PI_F * ay;
    out_alpha[p * 3 + 2] = INV_4PI_F * az;
}

// ---------------- df reduction: warp per point ----------------
__global__ void k_df(const float* __restrict__ y, const float* __restrict__ gy,
                     const float* __restrict__ B, const float* __restrict__ out_alpha,
                     float* __restrict__ out_df, float* __restrict__ out_cur, int n) {
    int tid = threadIdx.x;
    int p = blockIdx.x * 8 + (tid >> 5);
    int lane = tid & 31;
    if (p >= n) return;
    const float* yr = y + (size_t)p * 2048;
    const float* gr = gy + (size_t)p * 2048;
    float d0 = 0.f, d1 = 0.f, d2 = 0.f;
    for (int j = lane; j < 1024; j += 32) {
        float sv = yr[j], cv = yr[1024 + j];
        float gs = gr[j], gc = gr[1024 + j];
        float dp = gs * cv - gc * sv;   // d f / d proj_j
        d0 += B[j] * dp;
        d1 += B[1024 + j] * dp;
        d2 += B[2048 + j] * dp;
    }
#pragma unroll
    for (int o = 16; o; o >>= 1) {
        d0 += __shfl_xor_sync(0xffffffffu, d0, o);
        d1 += __shfl_xor_sync(0xffffffffu, d1, o);
        d2 += __shfl_xor_sync(0xffffffffu, d2, o);
    }
    if (lane == 0) {
        float df0 = TWO_PI_F * d0, df1 = TWO_PI_F * d1, df2 = TWO_PI_F * d2;
        out_df[p * 3 + 0] = df0;
        out_df[p * 3 + 1] = df1;
        out_df[p * 3 + 2] = df2;
        out_cur[p * 3 + 0] = df0 + out_alpha[p * 3 + 0];
        out_cur[p * 3 + 1] = df1 + out_alpha[p * 3 + 1];
        out_cur[p * 3 + 2] = df2 + out_alpha[p * 3 + 2];
    }
}

// ---------------- launcher ----------------
extern "C" void kernel_launch(void* const* d_in, const int* in_sizes, int n_in,
                              void* d_out, int out_size) {
    const float* x    = (const float*)d_in[0];
    const float* bdry = (const float*)d_in[1];
    const float* B    = (const float*)d_in[2];
    const float* W1   = (const float*)d_in[3];
    const float* b1   = (const float*)d_in[4];
    const float* W2   = (const float*)d_in[5];
    const float* b2   = (const float*)d_in[6];
    const float* W3   = (const float*)d_in[7];
    const float* b3   = (const float*)d_in[8];
    const float* W4   = (const float*)d_in[9];
    const float* b4   = (const float*)d_in[10];
    const float* W5   = (const float*)d_in[11];
    const float* b5   = (const float*)d_in[12];

    int n = in_sizes[0] / 3;
    int M = in_sizes[1] / 3;

    float* out = (float*)d_out;
    float* out_f     = out;
    float* out_cur   = out + (size_t)n;
    float* out_df    = out + (size_t)4 * n;
    float* out_alpha = out + (size_t)7 * n;

    void* pv;
    cudaGetSymbolAddress(&pv, d_W1T); float* W1T = (float*)pv;
    cudaGetSymbolAddress(&pv, d_W2T); float* W2T = (float*)pv;
    cudaGetSymbolAddress(&pv, d_W3T); float* W3T = (float*)pv;
    cudaGetSymbolAddress(&pv, d_W4T); float* W4T = (float*)pv;
    cudaGetSymbolAddress(&pv, d_y);   float* yb  = (float*)pv;
    cudaGetSymbolAddress(&pv, d_h);   float* hb  = (float*)pv;
    cudaGetSymbolAddress(&pv, d_s);   float* sb  = (float*)pv;
    cudaGetSymbolAddress(&pv, d_g);   float* gb  = (float*)pv;
    cudaGetSymbolAddress(&pv, d_gy);  float* gyb = (float*)pv;

    const size_t HS = (size_t)NMAX * 256;
    float *h1 = hb, *h2 = hb + HS, *h3 = hb + 2 * HS, *h4 = hb + 3 * HS;
    float *s1 = sb, *s2 = sb + HS, *s3 = sb + 2 * HS, *s4 = sb + 3 * HS;
    float *g0 = gb, *g1b = gb + HS;

    const int SMEM = (64 * 258 + 64 * 129) * 4;  // 99072
    cudaFuncSetAttribute(k_gemm<0>, cudaFuncAttributeMaxDynamicSharedMemorySize, SMEM);
    cudaFuncSetAttribute(k_gemm<1>, cudaFuncAttributeMaxDynamicSharedMemorySize, SMEM);
    cudaFuncSetAttribute(k_gemm<2>, cudaFuncAttributeMaxDynamicSharedMemorySize, SMEM);

    // weight transposes (forward reads rows of W^T)
    k_tr<<<(2048 * 256 + 255) / 256, 256>>>(W1, W1T, 2048, 256);
    k_tr<<<(256 * 256 + 255) / 256, 256>>>(W2, W2T, 256, 256);
    k_tr<<<(256 * 256 + 255) / 256, 256>>>(W3, W3T, 256, 256);
    k_tr<<<(256 * 256 + 255) / 256, 256>>>(W4, W4T, 256, 256);

    // RFF features
    k_y<<<(n * 1024 + 255) / 256, 256>>>(x, B, yb, n);

    dim3 gFwd((n + 127) / 128, 4);
    // forward
    k_gemm<1><<<gFwd, 256, SMEM>>>(yb, 2048, W1T, 2048, b1, nullptr, h1, s1, 256, 2048, n);
    k_gemm<1><<<gFwd, 256, SMEM>>>(h1, 256, W2T, 256, b2, nullptr, h2, s2, 256, 256, n);
    k_gemm<1><<<gFwd, 256, SMEM>>>(h2, 256, W3T, 256, b3, nullptr, h3, s3, 256, 256, n);
    k_gemm<1><<<gFwd, 256, SMEM>>>(h3, 256, W4T, 256, b4, nullptr, h4, s4, 256, 256, n);

    // head: f and g4 = W5 * s4
    k_head<<<(n + 7) / 8, 256>>>(h4, s4, W5, b5, out_f, g0, n);

    // backward through mid layers (reads rows of original W)
    k_gemm<2><<<gFwd, 256, SMEM>>>(g0, 256, W4, 256, nullptr, s3, g1b, nullptr, 256, 256, n);
    k_gemm<2><<<gFwd, 256, SMEM>>>(g1b, 256, W3, 256, nullptr, s2, g0, nullptr, 256, 256, n);
    k_gemm<2><<<gFwd, 256, SMEM>>>(g0, 256, W2, 256, nullptr, s1, g1b, nullptr, 256, 256, n);

    // gy = g1 @ W1^T  (rows of W1), full 2048 cols
    dim3 gGy((n + 127) / 128, 32);
    k_gemm<0><<<gGy, 256, SMEM>>>(g1b, 256, W1, 256, nullptr, nullptr, gyb, nullptr, 2048, 256, n);

    // alpha (Biot-Savart), then df / current
    k_biot<<<(n + 255) / 256, 256>>>(x, bdry, out_alpha, n, M);
    k_df<<<(n + 7) / 8, 256>>>(yb, gyb, B, out_alpha, out_df, out_cur, n);
}

// round 3
// speedup vs baseline: 2.8975x; 2.8975x over previous
#include <cuda_runtime.h>
#include <math.h>
#include <cstdint>

#define NMAX 65536
#define TWO_PI_F  6.283185307179586f
#define INV_4PI_F 0.07957747154594767f

// ---------------- scratch (__device__ globals; no allocation allowed) ----------------
__device__ float d_W1T[256 * 2048];
__device__ float d_W2T[256 * 256];
__device__ float d_W3T[256 * 256];
__device__ float d_W4T[256 * 256];
__device__ float d_y[(size_t)NMAX * 2048];   // [sin | cos] per point
__device__ float d_h[(size_t)4 * NMAX * 256];
__device__ float d_s[(size_t)4 * NMAX * 256];
__device__ float d_g[(size_t)2 * NMAX * 256];
__device__ float d_gy[(size_t)NMAX * 2048];  // dL/dy

// ---------------- helpers ----------------
__device__ __forceinline__ uint32_t to_tf32(float f) {
    uint32_t r; asm("cvt.rna.tf32.f32 %0, %1;" : "=r"(r) : "f"(f)); return r;
}
__device__ __forceinline__ void mma_tf32(float* d, const uint32_t* a, const uint32_t* b) {
    asm volatile(
        "mma.sync.aligned.m16n8k8.row.col.f32.tf32.tf32.f32 "
        "{%0,%1,%2,%3}, {%4,%5,%6,%7}, {%8,%9}, {%0,%1,%2,%3};"
        : "+f"(d[0]), "+f"(d[1]), "+f"(d[2]), "+f"(d[3])
        : "r"(a[0]), "r"(a[1]), "r"(a[2]), "r"(a[3]), "r"(b[0]), "r"(b[1]));
}
__device__ __forceinline__ float clip1(float v) { return fminf(fmaxf(v, -1.0f), 1.0f); }

// ---------------- transpose ----------------
__global__ void k_tr(const float* __restrict__ in, float* __restrict__ out, int R, int C) {
    int idx = blockIdx.x * blockDim.x + threadIdx.x;
    if (idx >= R * C) return;
    int r = idx / C, c = idx - r * C;
    out[(size_t)c * R + r] = in[idx];
}

// ---------------- RFF features (exact period-1 reduction + fast sincos) ----------------
__global__ void k_y(const float* __restrict__ x, const float* __restrict__ B,
                    float* __restrict__ y, int n) {
    int idx = blockIdx.x * blockDim.x + threadIdx.x;
    if (idx >= n * 1024) return;
    int p = idx >> 10, j = idx & 1023;
    float x0 = clip1(x[p * 3 + 0]);
    float x1 = clip1(x[p * 3 + 1]);
    float x2 = clip1(x[p * 3 + 2]);
    float t = x0 * B[j] + x1 * B[1024 + j] + x2 * B[2048 + j];
    float r = t - rintf(t);          // sin(2*pi*t) == sin(2*pi*r), exact period
    float arg = TWO_PI_F * r;        // |arg| <= pi
    float sv, cv;
    __sincosf(arg, &sv, &cv);
    y[(size_t)p * 2048 + j] = sv;
    y[(size_t)p * 2048 + 1024 + j] = cv;
}

// ---------------- tf32 mma.sync GEMM ----------------
// C[p, c] = sum_k A[p,k] * Bm[c*ldb + k]   (Bm rows are K-major per output col)
// Block tile M=128, N=256, K_stage=32; 8 warps (2M x 4N), warp tile 64x64.
// EPI 0: plain store. EPI 1: z=v+bias[c]; softplus->C, sigmoid->Cs. EPI 2: v*Sm -> C.
#define AS (128 * 36)
#define BS (256 * 36)

struct StageRegs { float4 a[4]; float4 b[8]; };

__device__ __forceinline__ void ld_stage(StageRegs& s,
        const float* __restrict__ A, int lda,
        const float* __restrict__ Bm, int ldb,
        int p0, int c0, int koff, int tid, int n) {
    const float* Ab = A + (size_t)p0 * lda + koff;
#pragma unroll
    for (int it = 0; it < 4; it++) {
        int lin = tid + 256 * it;
        int row = lin >> 3, q = (lin & 7) << 2;
        s.a[it] = (p0 + row < n) ? *(const float4*)(Ab + (size_t)row * lda + q)
                                 : make_float4(0.f, 0.f, 0.f, 0.f);
    }
    const float* Bb = Bm + (size_t)c0 * ldb + koff;
#pragma unroll
    for (int it = 0; it < 8; it++) {
        int lin = tid + 256 * it;
        int row = lin >> 3, q = (lin & 7) << 2;
        s.b[it] = *(const float4*)(Bb + (size_t)row * ldb + q);
    }
}

__device__ __forceinline__ void st_stage(const StageRegs& s,
        uint32_t* sA, uint32_t* sB, int tid) {
#pragma unroll
    for (int it = 0; it < 4; it++) {
        int lin = tid + 256 * it;
        int row = lin >> 3, q = (lin & 7) << 2;
        *(uint4*)(sA + row * 36 + q) = make_uint4(
            to_tf32(s.a[it].x), to_tf32(s.a[it].y), to_tf32(s.a[it].z), to_tf32(s.a[it].w));
    }
#pragma unroll
    for (int it = 0; it < 8; it++) {
        int lin = tid + 256 * it;
        int row = lin >> 3, q = (lin & 7) << 2;
        *(uint4*)(sB + row * 36 + q) = make_uint4(
            to_tf32(s.b[it].x), to_tf32(s.b[it].y), to_tf32(s.b[it].z), to_tf32(s.b[it].w));
    }
}

template <int EPI>
__global__ __launch_bounds__(256, 1)
void k_mma(const float* __restrict__ A, int lda,
           const float* __restrict__ Bm, int ldb,
           const float* __restrict__ bias, const float* __restrict__ Sm,
           float* __restrict__ C, float* __restrict__ Cs,
           int ldc, int K, int n) {
    extern __shared__ uint32_t smem[];
    uint32_t* sA = smem;            // [2][128*36]
    uint32_t* sB = smem + 2 * AS;   // [2][256*36]
    const int tid = threadIdx.x;
    const int p0 = blockIdx.x * 128;
    const int c0 = blockIdx.y * 256;
    const int wid = tid >> 5, lane = tid & 31;
    const int wm = (wid >> 2) * 64;   // warp M offset
    const int wn = (wid & 3) * 64;    // warp N offset
    const int tr = lane >> 2, tc = lane & 3;

    float acc[4][8][4];
#pragma unroll
    for (int mi = 0; mi < 4; mi++)
#pragma unroll
        for (int ni = 0; ni < 8; ni++)
#pragma unroll
            for (int q = 0; q < 4; q++) acc[mi][ni][q] = 0.0f;

    const int nst = K >> 5;
    StageRegs sreg;
    ld_stage(sreg, A, lda, Bm, ldb, p0, c0, 0, tid, n);
    st_stage(sreg, sA, sB, tid);
    __syncthreads();

    for (int i = 0; i < nst; i++) {
        if (i + 1 < nst) ld_stage(sreg, A, lda, Bm, ldb, p0, c0, (i + 1) * 32, tid, n);
        const uint32_t* cA = sA + (i & 1) * AS;
        const uint32_t* cB = sB + (i & 1) * BS;
#pragma unroll
        for (int k8 = 0; k8 < 4; k8++) {
            const int kc = k8 * 8;
            uint32_t af[4][4], bf[8][2];
#pragma unroll
            for (int mi = 0; mi < 4; mi++) {
                const uint32_t* base = cA + (wm + mi * 16 + tr) * 36 + kc + tc;
                af[mi][0] = base[0];
                af[mi][1] = base[8 * 36];
                af[mi][2] = base[4];
                af[mi][3] = base[8 * 36 + 4];
            }
#pragma unroll
            for (int ni = 0; ni < 8; ni++) {
                const uint32_t* base = cB + (wn + ni * 8 + tr) * 36 + kc + tc;
                bf[ni][0] = base[0];
                bf[ni][1] = base[4];
            }
#pragma unroll
            for (int mi = 0; mi < 4; mi++)
#pragma unroll
                for (int ni = 0; ni < 8; ni++)
                    mma_tf32(acc[mi][ni], af[mi], bf[ni]);
        }
        if (i + 1 < nst)
            st_stage(sreg, sA + ((i + 1) & 1) * AS, sB + ((i + 1) & 1) * BS, tid);
        __syncthreads();
    }

    // ---- epilogue: native mma accumulator layout, float2 stores ----
#pragma unroll
    for (int mi = 0; mi < 4; mi++) {
        const int r0 = p0 + wm + mi * 16 + tr;
#pragma unroll
        for (int ni = 0; ni < 8; ni++) {
            const int gc = c0 + wn + ni * 8 + 2 * tc;
            float2 bia = make_float2(0.f, 0.f);
            if (EPI == 1) bia = *(const float2*)(bias + gc);
#pragma unroll
            for (int half = 0; half < 2; half++) {
                const int p = r0 + 8 * half;
                if (p >= n) continue;
                float v0 = acc[mi][ni][2 * half];
                float v1 = acc[mi][ni][2 * half + 1];
                const size_t off = (size_t)p * ldc + gc;
                if (EPI == 0) {
                    *(float2*)(C + off) = make_float2(v0, v1);
                } else if (EPI == 1) {
                    float z0 = v0 + bia.x, z1 = v1 + bia.y;
                    float e0 = __expf(-fabsf(z0)), e1 = __expf(-fabsf(z1));
                    float h0 = fmaxf(z0, 0.f) + log1pf(e0);
                    float h1 = fmaxf(z1, 0.f) + log1pf(e1);
                    float s0 = (z0 >= 0.f) ? 1.f / (1.f + e0) : e0 / (1.f + e0);
                    float s1 = (z1 >= 0.f) ? 1.f / (1.f + e1) : e1 / (1.f + e1);
                    *(float2*)(C + off) = make_float2(h0, h1);
                    *(float2*)(Cs + off) = make_float2(s0, s1);
                } else {
                    float2 sm2 = *(const float2*)(Sm + off);
                    *(float2*)(C + off) = make_float2(v0 * sm2.x, v1 * sm2.y);
                }
            }
        }
    }
}

// ---------------- head: f = h4 . W5 + b5, g4 = W5 * s4 ----------------
__global__ void k_head(const float* __restrict__ h4, const float* __restrict__ s4,
                       const float* __restrict__ W5, const float* __restrict__ b5,
                       float* __restrict__ out_f, float* __restrict__ g4, int n) {
    __shared__ float sw[256];
    int tid = threadIdx.x;
    sw[tid] = W5[tid];
    __syncthreads();
    int p = blockIdx.x * 8 + (tid >> 5);
    int lane = tid & 31;
    if (p >= n) return;
    float acc = 0.f;
    const float* hr = h4 + (size_t)p * 256;
    const float* sr = s4 + (size_t)p * 256;
    float* gr = g4 + (size_t)p * 256;
#pragma unroll
    for (int i = lane; i < 256; i += 32) {
        float wv = sw[i];
        acc += hr[i] * wv;
        gr[i] = wv * sr[i];
    }
#pragma unroll
    for (int o = 16; o; o >>= 1) acc += __shfl_xor_sync(0xffffffffu, acc, o);
    if (lane == 0) out_f[p] = acc + b5[0];
}

// ---------------- Biot-Savart ----------------
__global__ void k_biot(const float* __restrict__ x, const float* __restrict__ bdry,
                       float* __restrict__ out_alpha, int n, int M) {
    __shared__ float bx[512], by[512], bz[512];
    __shared__ float sgx[512], sgy[512], sgz[512];
    __shared__ float smx[512], smy[512], smz[512];
    int tid = threadIdx.x;
    for (int m = tid; m < M; m += blockDim.x) {
        bx[m] = bdry[m * 3 + 0];
        by[m] = bdry[m * 3 + 1];
        bz[m] = bdry[m * 3 + 2];
    }
    __syncthreads();
    for (int m = tid; m < M; m += blockDim.x) {
        int m2 = (m + 1) == M ? 0 : m + 1;
        sgx[m] = bx[m2] - bx[m];
        sgy[m] = by[m2] - by[m];
        sgz[m] = bz[m2] - bz[m];
        smx[m] = 0.5f * (bx[m2] + bx[m]);
        smy[m] = 0.5f * (by[m2] + by[m]);
        smz[m] = 0.5f * (bz[m2] + bz[m]);
    }
    __syncthreads();
    int p = blockIdx.x * blockDim.x + tid;
    if (p >= n) return;
    float x0 = clip1(x[p * 3 + 0]);
    float x1 = clip1(x[p * 3 + 1]);
    float x2 = clip1(x[p * 3 + 2]);
    float ax = 0.f, ay = 0.f, az = 0.f;
    for (int m = 0; m < M; m++) {
        float dx = x0 - smx[m], dy = x1 - smy[m], dz = x2 - smz[m];
        float cxv = sgy[m] * dz - sgz[m] * dy;
        float cyv = sgz[m] * dx - sgx[m] * dz;
        float czv = sgx[m] * dy - sgy[m] * dx;
        float r2 = dx * dx + dy * dy + dz * dz;
        float inv = rsqrtf(r2);
        float w = inv * inv * inv;
        ax += cxv * w; ay += cyv * w; az += czv * w;
    }
    out_alpha[p * 3 + 0] = INV_4PI_F * ax;
    out_alpha[p * 3 + 1] = INV_4PI_F * ay;
    out_alpha[p * 3 + 2] = INV_4PI_F * az;
}

// ---------------- df reduction ----------------
__global__ void k_df(const float* __restrict__ y, const float* __restrict__ gy,
                     const float* __restrict__ B, const float* __restrict__ out_alpha,
                     float* __restrict__ out_df, float* __restrict__ out_cur, int n) {
    int tid = threadIdx.x;
    int p = blockIdx.x * 8 + (tid >> 5);
    int lane = tid & 31;
    if (p >= n) return;
    const float* yr = y + (size_t)p * 2048;
    const float* gr = gy + (size_t)p * 2048;
    float d0 = 0.f, d1 = 0.f, d2 = 0.f;
    for (int j = lane; j < 1024; j += 32) {
        float sv = yr[j], cv = yr[1024 + j];
        float gs = gr[j], gc = gr[1024 + j];
        float dp = gs * cv - gc * sv;
        d0 += B[j] * dp;
        d1 += B[1024 + j] * dp;
        d2 += B[2048 + j] * dp;
    }
#pragma unroll
    for (int o = 16; o; o >>= 1) {
        d0 += __shfl_xor_sync(0xffffffffu, d0, o);
        d1 += __shfl_xor_sync(0xffffffffu, d1, o);
        d2 += __shfl_xor_sync(0xffffffffu, d2, o);
    }
    if (lane == 0) {
        float df0 = TWO_PI_F * d0, df1 = TWO_PI_F * d1, df2 = TWO_PI_F * d2;
        out_df[p * 3 + 0] = df0;
        out_df[p * 3 + 1] = df1;
        out_df[p * 3 + 2] = df2;
        out_cur[p * 3 + 0] = df0 + out_alpha[p * 3 + 0];
        out_cur[p * 3 + 1] = df1 + out_alpha[p * 3 + 1];
        out_cur[p * 3 + 2] = df2 + out_alpha[p * 3 + 2];
    }
}

// ---------------- launcher ----------------
extern "C" void kernel_launch(void* const* d_in, const int* in_sizes, int n_in,
                              void* d_out, int out_size) {
    const float* x    = (const float*)d_in[0];
    const float* bdry = (const float*)d_in[1];
    const float* B    = (const float*)d_in[2];
    const float* W1   = (const float*)d_in[3];
    const float* b1   = (const float*)d_in[4];
    const float* W2   = (const float*)d_in[5];
    const float* b2   = (const float*)d_in[6];
    const float* W3   = (const float*)d_in[7];
    const float* b3   = (const float*)d_in[8];
    const float* W4   = (const float*)d_in[9];
    const float* b4   = (const float*)d_in[10];
    const float* W5   = (const float*)d_in[11];
    const float* b5   = (const float*)d_in[12];

    int n = in_sizes[0] / 3;
    int M = in_sizes[1] / 3;

    float* out = (float*)d_out;
    float* out_f     = out;
    float* out_cur   = out + (size_t)n;
    float* out_df    = out + (size_t)4 * n;
    float* out_alpha = out + (size_t)7 * n;

    void* pv;
    cudaGetSymbolAddress(&pv, d_W1T); float* W1T = (float*)pv;
    cudaGetSymbolAddress(&pv, d_W2T); float* W2T = (float*)pv;
    cudaGetSymbolAddress(&pv, d_W3T); float* W3T = (float*)pv;
    cudaGetSymbolAddress(&pv, d_W4T); float* W4T = (float*)pv;
    cudaGetSymbolAddress(&pv, d_y);   float* yb  = (float*)pv;
    cudaGetSymbolAddress(&pv, d_h);   float* hb  = (float*)pv;
    cudaGetSymbolAddress(&pv, d_s);   float* sb  = (float*)pv;
    cudaGetSymbolAddress(&pv, d_g);   float* gb  = (float*)pv;
    cudaGetSymbolAddress(&pv, d_gy);  float* gyb = (float*)pv;

    const size_t HS = (size_t)NMAX * 256;
    float *h1 = hb, *h2 = hb + HS, *h3 = hb + 2 * HS, *h4 = hb + 3 * HS;
    float *s1 = sb, *s2 = sb + HS, *s3 = sb + 2 * HS, *s4 = sb + 3 * HS;
    float *g0 = gb, *g1b = gb + HS;

    const int SMEM = (2 * AS + 2 * BS) * 4;  // 110592 bytes
    cudaFuncSetAttribute(k_mma<0>, cudaFuncAttributeMaxDynamicSharedMemorySize, SMEM);
    cudaFuncSetAttribute(k_mma<1>, cudaFuncAttributeMaxDynamicSharedMemorySize, SMEM);
    cudaFuncSetAttribute(k_mma<2>, cudaFuncAttributeMaxDynamicSharedMemorySize, SMEM);

    // weight transposes (forward reads rows of W^T)
    k_tr<<<(2048 * 256 + 255) / 256, 256>>>(W1, W1T, 2048, 256);
    k_tr<<<(256 * 256 + 255) / 256, 256>>>(W2, W2T, 256, 256);
    k_tr<<<(256 * 256 + 255) / 256, 256>>>(W3, W3T, 256, 256);
    k_tr<<<(256 * 256 + 255) / 256, 256>>>(W4, W4T, 256, 256);

    // RFF features
    k_y<<<(n * 1024 + 255) / 256, 256>>>(x, B, yb, n);

    dim3 gFwd((n + 127) / 128, 1);
    // forward
    k_mma<1><<<gFwd, 256, SMEM>>>(yb, 2048, W1T, 2048, b1, nullptr, h1, s1, 256, 2048, n);
    k_mma<1><<<gFwd, 256, SMEM>>>(h1, 256, W2T, 256, b2, nullptr, h2, s2, 256, 256, n);
    k_mma<1><<<gFwd, 256, SMEM>>>(h2, 256, W3T, 256, b3, nullptr, h3, s3, 256, 256, n);
    k_mma<1><<<gFwd, 256, SMEM>>>(h3, 256, W4T, 256, b4, nullptr, h4, s4, 256, 256, n);

    // head: f and g4 = W5 * s4
    k_head<<<(n + 7) / 8, 256>>>(h4, s4, W5, b5, out_f, g0, n);

    // backward through mid layers (reads rows of original W)
    k_mma<2><<<gFwd, 256, SMEM>>>(g0, 256, W4, 256, nullptr, s3, g1b, nullptr, 256, 256, n);
    k_mma<2><<<gFwd, 256, SMEM>>>(g1b, 256, W3, 256, nullptr, s2, g0, nullptr, 256, 256, n);
    k_mma<2><<<gFwd, 256, SMEM>>>(g0, 256, W2, 256, nullptr, s1, g1b, nullptr, 256, 256, n);

    // gy = g1 @ W1^T (rows of W1), N=2048 in 8 col tiles
    dim3 gGy((n + 127) / 128, 8);
    k_mma<0><<<gGy, 256, SMEM>>>(g1b, 256, W1, 256, nullptr, nullptr, gyb, nullptr, 2048, 256, n);

    // alpha (Biot-Savart), then df / current
    k_biot<<<(n + 255) / 256, 256>>>(x, bdry, out_alpha, n, M);
    k_df<<<(n + 7) / 8, 256>>>(yb, gyb, B, out_alpha, out_df, out_cur, n);
}

// round 4
// speedup vs baseline: 3.2582x; 1.1245x over previous
#include <cuda_runtime.h>
#include <math.h>
#include <cstdint>

#define NMAX 65536
#define TWO_PI_F  6.283185307179586f
#define INV_4PI_F 0.07957747154594767f

// ---------------- scratch (__device__ globals; no allocation allowed) ----------------
__device__ float d_W1T[2048 * 256];   // W1 transposed+rounded  [256][2048]
__device__ float d_W1P[2048 * 256];   // W1 rows permuted (sin/cos paired) + rounded [2048][256]
__device__ float d_W2T[256 * 256];
__device__ float d_W3T[256 * 256];
__device__ float d_W4T[256 * 256];
__device__ float d_W2R[256 * 256];    // rounded copies (bwd B operands)
__device__ float d_W3R[256 * 256];
__device__ float d_W4R[256 * 256];
__device__ float d_y[(size_t)NMAX * 2048];   // tf32-rounded [sin | cos]
__device__ float d_h[(size_t)4 * NMAX * 256];
__device__ float d_s[(size_t)4 * NMAX * 256];
__device__ float d_g[(size_t)2 * NMAX * 256];
__device__ float d_dfp[(size_t)8 * NMAX * 3];  // per-N-tile df partials

// ---------------- helpers ----------------
__device__ __forceinline__ uint32_t to_tf32(float f) {
    uint32_t r; asm("cvt.rna.tf32.f32 %0, %1;" : "=r"(r) : "f"(f)); return r;
}
__device__ __forceinline__ float round_tf32(float f) { return __uint_as_float(to_tf32(f)); }
__device__ __forceinline__ void mma_tf32(float* d, const uint32_t* a, const uint32_t* b) {
    asm volatile(
        "mma.sync.aligned.m16n8k8.row.col.f32.tf32.tf32.f32 "
        "{%0,%1,%2,%3}, {%4,%5,%6,%7}, {%8,%9}, {%0,%1,%2,%3};"
        : "+f"(d[0]), "+f"(d[1]), "+f"(d[2]), "+f"(d[3])
        : "r"(a[0]), "r"(a[1]), "r"(a[2]), "r"(a[3]), "r"(b[0]), "r"(b[1]));
}
__device__ __forceinline__ void cp_async16(uint32_t dst, const void* src, bool pred) {
    int sz = pred ? 16 : 0;
    asm volatile("cp.async.cg.shared.global [%0], [%1], 16, %2;"
                 :: "r"(dst), "l"(src), "r"(sz));
}
__device__ __forceinline__ void cp_commit() {
    asm volatile("cp.async.commit_group;" ::: "memory");
}
__device__ __forceinline__ float clip1(float v) { return fminf(fmaxf(v, -1.0f), 1.0f); }

// ---------------- weight prep ----------------
__global__ void k_tr(const float* __restrict__ in, float* __restrict__ out, int R, int C) {
    int idx = blockIdx.x * blockDim.x + threadIdx.x;
    if (idx >= R * C) return;
    int r = idx / C, c = idx - r * C;
    out[(size_t)c * R + r] = round_tf32(in[idx]);
}
__global__ void k_round(const float* __restrict__ in, float* __restrict__ out, int nelem) {
    int idx = blockIdx.x * blockDim.x + threadIdx.x;
    if (idx >= nelem) return;
    out[idx] = round_tf32(in[idx]);
}
// permute W1 rows: tile t of 256 rows = [sin j=128t..128t+127 | cos j'=1024+128t..]
__global__ void k_perm(const float* __restrict__ W1, float* __restrict__ out) {
    int idx = blockIdx.x * blockDim.x + threadIdx.x;
    if (idx >= 2048 * 256) return;
    int rp = idx >> 8, q = idx & 255;
    int t = rp >> 8, s = rp & 255;
    int j = (s < 128) ? (t * 128 + s) : (1024 + t * 128 + (s - 128));
    out[idx] = round_tf32(W1[(size_t)j * 256 + q]);
}

// ---------------- RFF features: tf32-rounded sin/cos ----------------
__global__ void k_y(const float* __restrict__ x, const float* __restrict__ B,
                    float* __restrict__ y, int n) {
    int idx = blockIdx.x * blockDim.x + threadIdx.x;
    if (idx >= n * 1024) return;
    int p = idx >> 10, j = idx & 1023;
    float x0 = clip1(x[p * 3 + 0]);
    float x1 = clip1(x[p * 3 + 1]);
    float x2 = clip1(x[p * 3 + 2]);
    float t = x0 * B[j] + x1 * B[1024 + j] + x2 * B[2048 + j];
    float r = t - rintf(t);
    float sv, cv;
    __sincosf(TWO_PI_F * r, &sv, &cv);
    y[(size_t)p * 2048 + j] = round_tf32(sv);
    y[(size_t)p * 2048 + 1024 + j] = round_tf32(cv);
}

// ---------------- tf32 mma.sync GEMM, cp.async 3-stage ----------------
// C[p, c] = sum_k A[p,k] * Bm[c*ldb + k]
// Block tile M=128, N=256, K_stage=32; 8 warps (2M x 4N), warp tile 64x64.
// EPI 1: z=v+bias[c]; round(softplus)->C, sigmoid->Cs.
// EPI 2: round(v*Sm) -> C.
// EPI 3: fused df contraction (gy x y x B_rff) -> dfpart, nothing else stored.
#define AS (128 * 36)
#define BS (256 * 36)
#define STG (AS + BS)

__device__ __forceinline__ void issue_stage(uint32_t sAb, uint32_t sBb,
        const float* __restrict__ A, int lda,
        const float* __restrict__ Bm, int ldb,
        int p0, int c0, int koff, int tid, int n) {
    const float* Ab = A + (size_t)p0 * lda + koff;
#pragma unroll
    for (int it = 0; it < 4; it++) {
        int lin = tid + 256 * it;
        int row = lin >> 3, q = (lin & 7) << 2;
        cp_async16(sAb + (uint32_t)(row * 36 + q) * 4, Ab + (size_t)row * lda + q, p0 + row < n);
    }
    const float* Bb = Bm + (size_t)c0 * ldb + koff;
#pragma unroll
    for (int it = 0; it < 8; it++) {
        int lin = tid + 256 * it;
        int row = lin >> 3, q = (lin & 7) << 2;
        cp_async16(sBb + (uint32_t)(row * 36 + q) * 4, Bb + (size_t)row * ldb + q, true);
    }
}

template <int EPI>
__global__ __launch_bounds__(256, 1)
void k_mma(const float* __restrict__ A, int lda,
           const float* __restrict__ Bm, int ldb,
           const float* __restrict__ bias, const float* __restrict__ Sm,
           float* __restrict__ C, float* __restrict__ Cs,
           int ldc, int K, int n,
           const float* __restrict__ Ybuf, const float* __restrict__ Brff,
           float* __restrict__ dfpart) {
    extern __shared__ uint32_t smem[];
    const int tid = threadIdx.x;
    const int p0 = blockIdx.x * 128;
    const int c0 = blockIdx.y * 256;
    const int wid = tid >> 5, lane = tid & 31;
    const int wm = (wid >> 2) * 64;
    const int wn = (wid & 3) * 64;
    const int tr = lane >> 2, tc = lane & 3;

    uint32_t smem_u32 = (uint32_t)__cvta_generic_to_shared(smem);

    float acc[4][8][4];
#pragma unroll
    for (int mi = 0; mi < 4; mi++)
#pragma unroll
        for (int ni = 0; ni < 8; ni++)
#pragma unroll
            for (int q = 0; q < 4; q++) acc[mi][ni][q] = 0.0f;

    const int nst = K >> 5;
    issue_stage(smem_u32, smem_u32 + AS * 4, A, lda, Bm, ldb, p0, c0, 0, tid, n);
    cp_commit();
    issue_stage(smem_u32 + STG * 4, smem_u32 + (STG + AS) * 4, A, lda, Bm, ldb, p0, c0, 32, tid, n);
    cp_commit();

    for (int i = 0; i < nst; i++) {
        if (i + 1 < nst) asm volatile("cp.async.wait_group 1;" ::: "memory");
        else             asm volatile("cp.async.wait_group 0;" ::: "memory");
        __syncthreads();
        if (i + 2 < nst) {
            int sl = (i + 2) % 3;
            issue_stage(smem_u32 + (uint32_t)sl * STG * 4, smem_u32 + (uint32_t)(sl * STG + AS) * 4,
                        A, lda, Bm, ldb, p0, c0, (i + 2) * 32, tid, n);
            cp_commit();
        }
        const uint32_t* cA = smem + (i % 3) * STG;
        const uint32_t* cB = cA + AS;
#pragma unroll
        for (int k8 = 0; k8 < 4; k8++) {
            const int kc = k8 * 8;
            uint32_t af[4][4], bf[8][2];
#pragma unroll
            for (int mi = 0; mi < 4; mi++) {
                const uint32_t* base = cA + (wm + mi * 16 + tr) * 36 + kc + tc;
                af[mi][0] = base[0];
                af[mi][1] = base[8 * 36];
                af[mi][2] = base[4];
                af[mi][3] = base[8 * 36 + 4];
            }
#pragma unroll
            for (int ni = 0; ni < 8; ni++) {
                const uint32_t* base = cB + (wn + ni * 8 + tr) * 36 + kc + tc;
                bf[ni][0] = base[0];
                bf[ni][1] = base[4];
            }
#pragma unroll
            for (int mi = 0; mi < 4; mi++)
#pragma unroll
                for (int ni = 0; ni < 8; ni++)
                    mma_tf32(acc[mi][ni], af[mi], bf[ni]);
        }
        __syncthreads();
    }

    if (EPI == 3) {
        // fused df: gy block (128 x 256 paired sin/cos cols) contracted with y, B_rff
        const int jt = c0 >> 1;               // 128 * blockIdx.y
        const bool coshalf = (wn >= 128);
        float sum3[4][2][3];
#pragma unroll
        for (int mi = 0; mi < 4; mi++)
#pragma unroll
            for (int hf = 0; hf < 2; hf++)
#pragma unroll
                for (int d = 0; d < 3; d++) sum3[mi][hf][d] = 0.f;

#pragma unroll
        for (int ni = 0; ni < 8; ni++) {
            int cl = wn + ni * 8 + 2 * tc;
            int j = jt + (coshalf ? cl - 128 : cl);
            float2 B0 = *(const float2*)(Brff + j);
            float2 B1 = *(const float2*)(Brff + 1024 + j);
            float2 B2 = *(const float2*)(Brff + 2048 + j);
            int yoff = coshalf ? j : (1024 + j);
#pragma unroll
            for (int mi = 0; mi < 4; mi++) {
#pragma unroll
                for (int hf = 0; hf < 2; hf++) {
                    int p = p0 + wm + mi * 16 + tr + 8 * hf;
                    float2 t2 = *(const float2*)(Ybuf + (size_t)p * 2048 + yoff);
                    float f0 = coshalf ? -t2.x : t2.x;
                    float f1 = coshalf ? -t2.y : t2.y;
                    float e0 = acc[mi][ni][2 * hf] * f0;
                    float e1 = acc[mi][ni][2 * hf + 1] * f1;
                    sum3[mi][hf][0] += e0 * B0.x + e1 * B0.y;
                    sum3[mi][hf][1] += e0 * B1.x + e1 * B1.y;
                    sum3[mi][hf][2] += e0 * B2.x + e1 * B2.y;
                }
            }
        }
        // reduce across tc (4 lanes), then across 4 wn groups via smem
        float* red = (float*)smem;   // [128][16]: p_local*16 + d*4 + wn_group
        __syncthreads();
#pragma unroll
        for (int mi = 0; mi < 4; mi++)
#pragma unroll
            for (int hf = 0; hf < 2; hf++)
#pragma unroll
                for (int d = 0; d < 3; d++) {
                    float v = sum3[mi][hf][d];
                    v += __shfl_xor_sync(0xffffffffu, v, 1);
                    v += __shfl_xor_sync(0xffffffffu, v, 2);
                    if (tc == 0) {
                        int p_local = wm + mi * 16 + tr + 8 * hf;
                        red[p_local * 16 + d * 4 + (wn >> 6)] = v;
                    }
                }
        __syncthreads();
        if (tid < 128) {
            int p = p0 + tid;
#pragma unroll
            for (int d = 0; d < 3; d++) {
                float s = red[tid * 16 + d * 4 + 0] + red[tid * 16 + d * 4 + 1] +
                          red[tid * 16 + d * 4 + 2] + red[tid * 16 + d * 4 + 3];
                dfpart[((size_t)blockIdx.y * NMAX + p) * 3 + d] = TWO_PI_F * s;
            }
        }
        return;
    }

    // ---- EPI 1 / 2 epilogue ----
#pragma unroll
    for (int mi = 0; mi < 4; mi++) {
        const int r0 = p0 + wm + mi * 16 + tr;
#pragma unroll
        for (int ni = 0; ni < 8; ni++) {
            const int gc = c0 + wn + ni * 8 + 2 * tc;
            float2 bia = make_float2(0.f, 0.f);
            if (EPI == 1) bia = *(const float2*)(bias + gc);
#pragma unroll
            for (int hf = 0; hf < 2; hf++) {
                const int p = r0 + 8 * hf;
                if (p >= n) continue;
                float v0 = acc[mi][ni][2 * hf];
                float v1 = acc[mi][ni][2 * hf + 1];
                const size_t off = (size_t)p * ldc + gc;
                if (EPI == 1) {
                    float z0 = v0 + bia.x, z1 = v1 + bia.y;
                    float e0 = __expf(-fabsf(z0)), e1 = __expf(-fabsf(z1));
                    float h0 = fmaxf(z0, 0.f) + log1pf(e0);
                    float h1 = fmaxf(z1, 0.f) + log1pf(e1);
                    float s0 = (z0 >= 0.f) ? 1.f / (1.f + e0) : e0 / (1.f + e0);
                    float s1 = (z1 >= 0.f) ? 1.f / (1.f + e1) : e1 / (1.f + e1);
                    *(float2*)(C + off) = make_float2(round_tf32(h0), round_tf32(h1));
                    *(float2*)(Cs + off) = make_float2(s0, s1);
                } else {
                    float2 sm2 = *(const float2*)(Sm + off);
                    *(float2*)(C + off) =
                        make_float2(round_tf32(v0 * sm2.x), round_tf32(v1 * sm2.y));
                }
            }
        }
    }
}

// ---------------- head: f = h4 . W5 + b5, g4 = round(W5 * s4) ----------------
__global__ void k_head(const float* __restrict__ h4, const float* __restrict__ s4,
                       const float* __restrict__ W5, const float* __restrict__ b5,
                       float* __restrict__ out_f, float* __restrict__ g4, int n) {
    __shared__ float sw[256];
    int tid = threadIdx.x;
    sw[tid] = W5[tid];
    __syncthreads();
    int p = blockIdx.x * 8 + (tid >> 5);
    int lane = tid & 31;
    if (p >= n) return;
    float acc = 0.f;
    const float* hr = h4 + (size_t)p * 256;
    const float* sr = s4 + (size_t)p * 256;
    float* gr = g4 + (size_t)p * 256;
#pragma unroll
    for (int i = lane; i < 256; i += 32) {
        float wv = sw[i];
        acc += hr[i] * wv;
        gr[i] = round_tf32(wv * sr[i]);
    }
#pragma unroll
    for (int o = 16; o; o >>= 1) acc += __shfl_xor_sync(0xffffffffu, acc, o);
    if (lane == 0) out_f[p] = acc + b5[0];
}

// ---------------- Biot-Savart ----------------
__global__ void k_biot(const float* __restrict__ x, const float* __restrict__ bdry,
                       float* __restrict__ out_alpha, int n, int M) {
    __shared__ float bx[512], by[512], bz[512];
    __shared__ float sgx[512], sgy[512], sgz[512];
    __shared__ float smx[512], smy[512], smz[512];
    int tid = threadIdx.x;
    for (int m = tid; m < M; m += blockDim.x) {
        bx[m] = bdry[m * 3 + 0];
        by[m] = bdry[m * 3 + 1];
        bz[m] = bdry[m * 3 + 2];
    }
    __syncthreads();
    for (int m = tid; m < M; m += blockDim.x) {
        int m2 = (m + 1) == M ? 0 : m + 1;
        sgx[m] = bx[m2] - bx[m];
        sgy[m] = by[m2] - by[m];
        sgz[m] = bz[m2] - bz[m];
        smx[m] = 0.5f * (bx[m2] + bx[m]);
        smy[m] = 0.5f * (by[m2] + by[m]);
        smz[m] = 0.5f * (bz[m2] + bz[m]);
    }
    __syncthreads();
    int p = blockIdx.x * blockDim.x + tid;
    if (p >= n) return;
    float x0 = clip1(x[p * 3 + 0]);
    float x1 = clip1(x[p * 3 + 1]);
    float x2 = clip1(x[p * 3 + 2]);
    float ax = 0.f, ay = 0.f, az = 0.f;
    for (int m = 0; m < M; m++) {
        float dx = x0 - smx[m], dy = x1 - smy[m], dz = x2 - smz[m];
        float cxv = sgy[m] * dz - sgz[m] * dy;
        float cyv = sgz[m] * dx - sgx[m] * dz;
        float czv = sgx[m] * dy - sgy[m] * dx;
        float r2 = dx * dx + dy * dy + dz * dz;
        float inv = rsqrtf(r2);
        float w = inv * inv * inv;
        ax += cxv * w; ay += cyv * w; az += czv * w;
    }
    out_alpha[p * 3 + 0] = INV_4PI_F * ax;
    out_alpha[p * 3 + 1] = INV_4PI_F * ay;
    out_alpha[p * 3 + 2] = INV_4PI_F * az;
}

// ---------------- finish: df = sum of 8 partials (fixed order), cur = df + alpha ----------------
__global__ void k_finish(const float* __restrict__ part, const float* __restrict__ alpha,
                         float* __restrict__ out_df, float* __restrict__ out_cur, int n) {
    int p = blockIdx.x * blockDim.x + threadIdx.x;
    if (p >= n) return;
#pragma unroll
    for (int d = 0; d < 3; d++) {
        float s = 0.f;
#pragma unroll
        for (int t = 0; t < 8; t++) s += part[((size_t)t * NMAX + p) * 3 + d];
        out_df[p * 3 + d] = s;
        out_cur[p * 3 + d] = s + alpha[p * 3 + d];
    }
}

// ---------------- launcher ----------------
extern "C" void kernel_launch(void* const* d_in, const int* in_sizes, int n_in,
                              void* d_out, int out_size) {
    const float* x    = (const float*)d_in[0];
    const float* bdry = (const float*)d_in[1];
    const float* B    = (const float*)d_in[2];
    const float* W1   = (const float*)d_in[3];
    const float* b1   = (const float*)d_in[4];
    const float* W2   = (const float*)d_in[5];
    const float* b2   = (const float*)d_in[6];
    const float* W3   = (const float*)d_in[7];
    const float* b3   = (const float*)d_in[8];
    const float* W4   = (const float*)d_in[9];
    const float* b4   = (const float*)d_in[10];
    const float* W5   = (const float*)d_in[11];
    const float* b5   = (const float*)d_in[12];

    int n = in_sizes[0] / 3;
    int M = in_sizes[1] / 3;

    float* out = (float*)d_out;
    float* out_f     = out;
    float* out_cur   = out + (size_t)n;
    float* out_df    = out + (size_t)4 * n;
    float* out_alpha = out + (size_t)7 * n;

    void* pv;
    cudaGetSymbolAddress(&pv, d_W1T); float* W1T = (float*)pv;
    cudaGetSymbolAddress(&pv, d_W1P); float* W1P = (float*)pv;
    cudaGetSymbolAddress(&pv, d_W2T); float* W2T = (float*)pv;
    cudaGetSymbolAddress(&pv, d_W3T); float* W3T = (float*)pv;
    cudaGetSymbolAddress(&pv, d_W4T); float* W4T = (float*)pv;
    cudaGetSymbolAddress(&pv, d_W2R); float* W2R = (float*)pv;
    cudaGetSymbolAddress(&pv, d_W3R); float* W3R = (float*)pv;
    cudaGetSymbolAddress(&pv, d_W4R); float* W4R = (float*)pv;
    cudaGetSymbolAddress(&pv, d_y);   float* yb  = (float*)pv;
    cudaGetSymbolAddress(&pv, d_h);   float* hb  = (float*)pv;
    cudaGetSymbolAddress(&pv, d_s);   float* sb  = (float*)pv;
    cudaGetSymbolAddress(&pv, d_g);   float* gb  = (float*)pv;
    cudaGetSymbolAddress(&pv, d_dfp); float* dfp = (float*)pv;

    const size_t HS = (size_t)NMAX * 256;
    float *h1 = hb, *h2 = hb + HS, *h3 = hb + 2 * HS, *h4 = hb + 3 * HS;
    float *s1 = sb, *s2 = sb + HS, *s3 = sb + 2 * HS, *s4 = sb + 3 * HS;
    float *g0 = gb, *g1b = gb + HS;

    const int SMEM = 3 * STG * 4;  // 165888 bytes
    cudaFuncSetAttribute(k_mma<1>, cudaFuncAttributeMaxDynamicSharedMemorySize, SMEM);
    cudaFuncSetAttribute(k_mma<2>, cudaFuncAttributeMaxDynamicSharedMemorySize, SMEM);
    cudaFuncSetAttribute(k_mma<3>, cudaFuncAttributeMaxDynamicSharedMemorySize, SMEM);

    // weight prep (rounded to tf32 at source)
    k_tr<<<(2048 * 256 + 255) / 256, 256>>>(W1, W1T, 2048, 256);
    k_tr<<<(256 * 256 + 255) / 256, 256>>>(W2, W2T, 256, 256);
    k_tr<<<(256 * 256 + 255) / 256, 256>>>(W3, W3T, 256, 256);
    k_tr<<<(256 * 256 + 255) / 256, 256>>>(W4, W4T, 256, 256);
    k_round<<<(256 * 256 + 255) / 256, 256>>>(W2, W2R, 256 * 256);
    k_round<<<(256 * 256 + 255) / 256, 256>>>(W3, W3R, 256 * 256);
    k_round<<<(256 * 256 + 255) / 256, 256>>>(W4, W4R, 256 * 256);
    k_perm<<<(2048 * 256 + 255) / 256, 256>>>(W1, W1P);

    // RFF features (rounded)
    k_y<<<(n * 1024 + 255) / 256, 256>>>(x, B, yb, n);

    dim3 gFwd((n + 127) / 128, 1);
    // forward
    k_mma<1><<<gFwd, 256, SMEM>>>(yb, 2048, W1T, 2048, b1, nullptr, h1, s1, 256, 2048, n, nullptr, nullptr, nullptr);
    k_mma<1><<<gFwd, 256, SMEM>>>(h1, 256, W2T, 256, b2, nullptr, h2, s2, 256, 256, n, nullptr, nullptr, nullptr);
    k_mma<1><<<gFwd, 256, SMEM>>>(h2, 256, W3T, 256, b3, nullptr, h3, s3, 256, 256, n, nullptr, nullptr, nullptr);
    k_mma<1><<<gFwd, 256, SMEM>>>(h3, 256, W4T, 256, b4, nullptr, h4, s4, 256, 256, n, nullptr, nullptr, nullptr);

    // head
    k_head<<<(n + 7) / 8, 256>>>(h4, s4, W5, b5, out_f, g0, n);

    // backward through mid layers
    k_mma<2><<<gFwd, 256, SMEM>>>(g0, 256, W4R, 256, nullptr, s3, g1b, nullptr, 256, 256, n, nullptr, nullptr, nullptr);
    k_mma<2><<<gFwd, 256, SMEM>>>(g1b, 256, W3R, 256, nullptr, s2, g0, nullptr, 256, 256, n, nullptr, nullptr, nullptr);
    k_mma<2><<<gFwd, 256, SMEM>>>(g0, 256, W2R, 256, nullptr, s1, g1b, nullptr, 256, 256, n, nullptr, nullptr, nullptr);

    // alpha (independent)
    k_biot<<<(n + 255) / 256, 256>>>(x, bdry, out_alpha, n, M);

    // gy GEMM fused with df contraction (8 paired N-tiles)
    dim3 gGy((n + 127) / 128, 8);
    k_mma<3><<<gGy, 256, SMEM>>>(g1b, 256, W1P, 256, nullptr, nullptr, nullptr, nullptr, 256, 256, n, yb, B, dfp);

    // df = sum partials; current = df + alpha
    k_finish<<<(n + 255) / 256, 256>>>(dfp, out_alpha, out_df, out_cur, n);
}

// round 5
// speedup vs baseline: 3.4567x; 1.0609x over previous
#include <cuda_runtime.h>
#include <math.h>
#include <cstdint>

#define NMAX 65536
#define TWO_PI_F  6.283185307179586f
#define PI_F      3.14159265358979f
#define INV_4PI_F 0.07957747154594767f

// ---------------- scratch ----------------
__device__ float d_W1T[2048 * 256];
__device__ float d_W1P[2048 * 256];
__device__ float d_WmidT[3 * 256 * 256];  // W2T | W3T | W4T (rounded)
__device__ float d_WmidR[3 * 256 * 256];  // W2R | W3R | W4R (rounded)
__device__ float d_y[(size_t)NMAX * 2048];
__device__ float d_h[(size_t)4 * NMAX * 256];
__device__ float d_s[(size_t)4 * NMAX * 256];
__device__ float d_g[(size_t)2 * NMAX * 256];
__device__ float d_dfp[(size_t)8 * NMAX * 3];

// ---------------- helpers ----------------
__device__ __forceinline__ uint32_t to_tf32(float f) {
    uint32_t r; asm("cvt.rna.tf32.f32 %0, %1;" : "=r"(r) : "f"(f)); return r;
}
__device__ __forceinline__ float round_tf32(float f) { return __uint_as_float(to_tf32(f)); }
__device__ __forceinline__ void mma_tf32(float* d, const uint32_t* a, const uint32_t* b) {
    asm volatile(
        "mma.sync.aligned.m16n8k8.row.col.f32.tf32.tf32.f32 "
        "{%0,%1,%2,%3}, {%4,%5,%6,%7}, {%8,%9}, {%0,%1,%2,%3};"
        : "+f"(d[0]), "+f"(d[1]), "+f"(d[2]), "+f"(d[3])
        : "r"(a[0]), "r"(a[1]), "r"(a[2]), "r"(a[3]), "r"(b[0]), "r"(b[1]));
}
__device__ __forceinline__ void cp_async16(uint32_t dst, const void* src, bool pred) {
    int sz = pred ? 16 : 0;
    asm volatile("cp.async.cg.shared.global [%0], [%1], 16, %2;"
                 :: "r"(dst), "l"(src), "r"(sz));
}
__device__ __forceinline__ void cp_commit() {
    asm volatile("cp.async.commit_group;" ::: "memory");
}
__device__ __forceinline__ float clip1(float v) { return fminf(fmaxf(v, -1.0f), 1.0f); }

// sin/cos of 2*pi*r for r in [-0.5, 0.5] via half-angle Taylor (err < 4e-5)
__device__ __forceinline__ void sincos2pi_poly(float r, float* s, float* c) {
    float x = PI_F * r;               // [-pi/2, pi/2]
    float t = x * x;
    float sp = -1.0f / 5040.0f + t * (1.0f / 362880.0f);
    sp = 1.0f / 120.0f + t * sp;
    sp = -1.0f / 6.0f + t * sp;
    sp = x + x * t * sp;              // sin(x)
    float cp = 1.0f / 40320.0f;
    cp = -1.0f / 720.0f + t * cp;
    cp = 1.0f / 24.0f + t * cp;
    cp = -0.5f + t * cp;
    cp = 1.0f + t * cp;               // cos(x)
    float u = sp * cp;
    *s = u + u;                       // sin(2x)
    *c = fmaf(-2.0f * sp, sp, 1.0f);  // cos(2x)
}

// ---------------- weight prep ----------------
__global__ void k_tr(const float* __restrict__ in, float* __restrict__ out, int R, int C) {
    int idx = blockIdx.x * blockDim.x + threadIdx.x;
    if (idx >= R * C) return;
    int r = idx / C, c = idx - r * C;
    out[(size_t)c * R + r] = round_tf32(in[idx]);
}
__global__ void k_prep_mid(const float* __restrict__ W2, const float* __restrict__ W3,
                           const float* __restrict__ W4,
                           float* __restrict__ outT, float* __restrict__ outR) {
    int idx = blockIdx.x * blockDim.x + threadIdx.x;
    if (idx >= 3 * 65536) return;
    int m = idx >> 16, e = idx & 65535;
    const float* W = (m == 0) ? W2 : (m == 1) ? W3 : W4;
    float v = round_tf32(W[e]);
    outR[idx] = v;
    int r = e >> 8, c = e & 255;
    outT[(m << 16) + c * 256 + r] = v;
}
__global__ void k_perm(const float* __restrict__ W1, float* __restrict__ out) {
    int idx = blockIdx.x * blockDim.x + threadIdx.x;
    if (idx >= 2048 * 256) return;
    int rp = idx >> 8, q = idx & 255;
    int t = rp >> 8, s = rp & 255;
    int j = (s < 128) ? (t * 128 + s) : (1024 + t * 128 + (s - 128));
    out[idx] = round_tf32(W1[(size_t)j * 256 + q]);
}

// ---------------- RFF features: 4 j per thread, mixed MUFU/poly pipes ----------------
__global__ void k_y(const float* __restrict__ x, const float* __restrict__ B,
                    float* __restrict__ y, int n) {
    int idx = blockIdx.x * blockDim.x + threadIdx.x;
    if (idx >= n * 256) return;
    int p = idx >> 8, j0 = (idx & 255) << 2;
    float x0 = clip1(x[p * 3 + 0]);
    float x1 = clip1(x[p * 3 + 1]);
    float x2 = clip1(x[p * 3 + 2]);
    float4 B0 = *(const float4*)(B + j0);
    float4 B1 = *(const float4*)(B + 1024 + j0);
    float4 B2 = *(const float4*)(B + 2048 + j0);
    float tv[4], sv[4], cv[4];
    tv[0] = x0 * B0.x + x1 * B1.x + x2 * B2.x;
    tv[1] = x0 * B0.y + x1 * B1.y + x2 * B2.y;
    tv[2] = x0 * B0.z + x1 * B1.z + x2 * B2.z;
    tv[3] = x0 * B0.w + x1 * B1.w + x2 * B2.w;
    bool mufu = (((idx >> 5) % 3) == 0);   // 1/3 of warps: MUFU pipe; rest: FMA pipe
#pragma unroll
    for (int q = 0; q < 4; q++) {
        float r = tv[q] - rintf(tv[q]);
        if (mufu) __sincosf(TWO_PI_F * r, &sv[q], &cv[q]);
        else sincos2pi_poly(r, &sv[q], &cv[q]);
        sv[q] = round_tf32(sv[q]);
        cv[q] = round_tf32(cv[q]);
    }
    *(float4*)(y + (size_t)p * 2048 + j0) = make_float4(sv[0], sv[1], sv[2], sv[3]);
    *(float4*)(y + (size_t)p * 2048 + 1024 + j0) = make_float4(cv[0], cv[1], cv[2], cv[3]);
}

// ---------------- tf32 mma.sync GEMM, cp.async 3-stage, LDS.64 frags ----------------
#define LDSW 40
#define AS (128 * LDSW)
#define BS (256 * LDSW)
#define STG (AS + BS)

__device__ __forceinline__ void issue_stage(uint32_t sAb, uint32_t sBb,
        const float* __restrict__ A, int lda,
        const float* __restrict__ Bm, int ldb,
        int p0, int c0, int koff, int tid, int n) {
    const float* Ab = A + (size_t)p0 * lda + koff;
#pragma unroll
    for (int it = 0; it < 4; it++) {
        int lin = tid + 256 * it;
        int row = lin >> 3, q = (lin & 7) << 2;
        cp_async16(sAb + (uint32_t)(row * LDSW + q) * 4, Ab + (size_t)row * lda + q, p0 + row < n);
    }
    const float* Bb = Bm + (size_t)c0 * ldb + koff;
#pragma unroll
    for (int it = 0; it < 8; it++) {
        int lin = tid + 256 * it;
        int row = lin >> 3, q = (lin & 7) << 2;
        cp_async16(sBb + (uint32_t)(row * LDSW + q) * 4, Bb + (size_t)row * ldb + q, true);
    }
}

// EPI 1: z=v+bias; softplus->C (rounded iff rndOut), sigmoid->Cs.
// EPI 2: round(v*Sm)->C.  EPI 3: fused df contraction.
template <int EPI>
__global__ __launch_bounds__(256, 1)
void k_mma(const float* __restrict__ A, int lda,
           const float* __restrict__ Bm, int ldb,
           const float* __restrict__ bias, const float* __restrict__ Sm,
           float* __restrict__ C, float* __restrict__ Cs,
           int ldc, int K, int n, int rndOut,
           const float* __restrict__ Ybuf, const float* __restrict__ Brff,
           float* __restrict__ dfpart) {
    extern __shared__ uint32_t smem[];
    const int tid = threadIdx.x;
    const int p0 = blockIdx.x * 128;
    const int c0 = blockIdx.y * 256;
    const int wid = tid >> 5, lane = tid & 31;
    const int wm = (wid >> 2) * 64;
    const int wn = (wid & 3) * 64;
    const int tr = lane >> 2, tc = lane & 3;

    uint32_t smem_u32 = (uint32_t)__cvta_generic_to_shared(smem);

    float acc[4][8][4];
#pragma unroll
    for (int mi = 0; mi < 4; mi++)
#pragma unroll
        for (int ni = 0; ni < 8; ni++)
#pragma unroll
            for (int q = 0; q < 4; q++) acc[mi][ni][q] = 0.0f;

    const int nst = K >> 5;
    issue_stage(smem_u32, smem_u32 + AS * 4, A, lda, Bm, ldb, p0, c0, 0, tid, n);
    cp_commit();
    issue_stage(smem_u32 + STG * 4, smem_u32 + (STG + AS) * 4, A, lda, Bm, ldb, p0, c0, 32, tid, n);
    cp_commit();

    for (int i = 0; i < nst; i++) {
        if (i + 1 < nst) asm volatile("cp.async.wait_group 1;" ::: "memory");
        else             asm volatile("cp.async.wait_group 0;" ::: "memory");
        __syncthreads();
        if (i + 2 < nst) {
            int sl = (i + 2) % 3;
            issue_stage(smem_u32 + (uint32_t)sl * STG * 4, smem_u32 + (uint32_t)(sl * STG + AS) * 4,
                        A, lda, Bm, ldb, p0, c0, (i + 2) * 32, tid, n);
            cp_commit();
        }
        const uint32_t* cA = smem + (i % 3) * STG;
        const uint32_t* cB = cA + AS;
        // k-slot permutation: thread (tc) consumes physical k = kc+2tc, kc+2tc+1
        // (identical permutation on A and B -> same dot product)
#pragma unroll
        for (int k8 = 0; k8 < 4; k8++) {
            const int kc = k8 * 8 + 2 * tc;
            uint32_t af[4][4], bf[8][2];
#pragma unroll
            for (int mi = 0; mi < 4; mi++) {
                const uint32_t* base = cA + (wm + mi * 16 + tr) * LDSW + kc;
                uint2 lo = *(const uint2*)base;
                uint2 hi = *(const uint2*)(base + 8 * LDSW);
                af[mi][0] = lo.x; af[mi][1] = hi.x; af[mi][2] = lo.y; af[mi][3] = hi.y;
            }
#pragma unroll
            for (int ni = 0; ni < 8; ni++) {
                uint2 b2 = *(const uint2*)(cB + (wn + ni * 8 + tr) * LDSW + kc);
                bf[ni][0] = b2.x; bf[ni][1] = b2.y;
            }
#pragma unroll
            for (int mi = 0; mi < 4; mi++)
#pragma unroll
                for (int ni = 0; ni < 8; ni++)
                    mma_tf32(acc[mi][ni], af[mi], bf[ni]);
        }
        __syncthreads();
    }

    if (EPI == 3) {
        const int jt = c0 >> 1;
        const bool coshalf = (wn >= 128);
        float sum3[4][2][3];
#pragma unroll
        for (int mi = 0; mi < 4; mi++)
#pragma unroll
            for (int hf = 0; hf < 2; hf++)
#pragma unroll
                for (int d = 0; d < 3; d++) sum3[mi][hf][d] = 0.f;

#pragma unroll
        for (int ni = 0; ni < 8; ni++) {
            int cl = wn + ni * 8 + 2 * tc;
            int j = jt + (coshalf ? cl - 128 : cl);
            float2 B0 = *(const float2*)(Brff + j);
            float2 B1 = *(const float2*)(Brff + 1024 + j);
            float2 B2 = *(const float2*)(Brff + 2048 + j);
            int yoff = coshalf ? j : (1024 + j);
#pragma unroll
            for (int mi = 0; mi < 4; mi++) {
#pragma unroll
                for (int hf = 0; hf < 2; hf++) {
                    int p = p0 + wm + mi * 16 + tr + 8 * hf;
                    float2 t2 = *(const float2*)(Ybuf + (size_t)p * 2048 + yoff);
                    float f0 = coshalf ? -t2.x : t2.x;
                    float f1 = coshalf ? -t2.y : t2.y;
                    float e0 = acc[mi][ni][2 * hf] * f0;
                    float e1 = acc[mi][ni][2 * hf + 1] * f1;
                    sum3[mi][hf][0] += e0 * B0.x + e1 * B0.y;
                    sum3[mi][hf][1] += e0 * B1.x + e1 * B1.y;
                    sum3[mi][hf][2] += e0 * B2.x + e1 * B2.y;
                }
            }
        }
        float* red = (float*)smem;
        __syncthreads();
#pragma unroll
        for (int mi = 0; mi < 4; mi++)
#pragma unroll
            for (int hf = 0; hf < 2; hf++)
#pragma unroll
                for (int d = 0; d < 3; d++) {
                    float v = sum3[mi][hf][d];
                    v += __shfl_xor_sync(0xffffffffu, v, 1);
                    v += __shfl_xor_sync(0xffffffffu, v, 2);
                    if (tc == 0) {
                        int p_local = wm + mi * 16 + tr + 8 * hf;
                        red[p_local * 16 + d * 4 + (wn >> 6)] = v;
                    }
                }
        __syncthreads();
        if (tid < 128) {
            int p = p0 + tid;
#pragma unroll
            for (int d = 0; d < 3; d++) {
                float s = red[tid * 16 + d * 4 + 0] + red[tid * 16 + d * 4 + 1] +
                          red[tid * 16 + d * 4 + 2] + red[tid * 16 + d * 4 + 3];
                dfpart[((size_t)blockIdx.y * NMAX + p) * 3 + d] = TWO_PI_F * s;
            }
        }
        return;
    }

#pragma unroll
    for (int mi = 0; mi < 4; mi++) {
        const int r0 = p0 + wm + mi * 16 + tr;
#pragma unroll
        for (int ni = 0; ni < 8; ni++) {
            const int gc = c0 + wn + ni * 8 + 2 * tc;
            float2 bia = make_float2(0.f, 0.f);
            if (EPI == 1) bia = *(const float2*)(bias + gc);
#pragma unroll
            for (int hf = 0; hf < 2; hf++) {
                const int p = r0 + 8 * hf;
                if (p >= n) continue;
                float v0 = acc[mi][ni][2 * hf];
                float v1 = acc[mi][ni][2 * hf + 1];
                const size_t off = (size_t)p * ldc + gc;
                if (EPI == 1) {
                    float z0 = v0 + bia.x, z1 = v1 + bia.y;
                    float e0 = __expf(-fabsf(z0)), e1 = __expf(-fabsf(z1));
                    float h0 = fmaxf(z0, 0.f) + log1pf(e0);
                    float h1 = fmaxf(z1, 0.f) + log1pf(e1);
                    float s0 = (z0 >= 0.f) ? 1.f / (1.f + e0) : e0 / (1.f + e0);
                    float s1 = (z1 >= 0.f) ? 1.f / (1.f + e1) : e1 / (1.f + e1);
                    if (rndOut) { h0 = round_tf32(h0); h1 = round_tf32(h1); }
                    *(float2*)(C + off) = make_float2(h0, h1);
                    *(float2*)(Cs + off) = make_float2(s0, s1);
                } else {
                    float2 sm2 = *(const float2*)(Sm + off);
                    *(float2*)(C + off) =
                        make_float2(round_tf32(v0 * sm2.x), round_tf32(v1 * sm2.y));
                }
            }
        }
    }
}

// ---------------- head ----------------
__global__ void k_head(const float* __restrict__ h4, const float* __restrict__ s4,
                       const float* __restrict__ W5, const float* __restrict__ b5,
                       float* __restrict__ out_f, float* __restrict__ g4, int n) {
    __shared__ float sw[256];
    int tid = threadIdx.x;
    sw[tid] = W5[tid];
    __syncthreads();
    int p = blockIdx.x * 8 + (tid >> 5);
    int lane = tid & 31;
    if (p >= n) return;
    float acc = 0.f;
    const float* hr = h4 + (size_t)p * 256;
    const float* sr = s4 + (size_t)p * 256;
    float* gr = g4 + (size_t)p * 256;
#pragma unroll
    for (int i = lane; i < 256; i += 32) {
        float wv = sw[i];
        acc += hr[i] * wv;
        gr[i] = round_tf32(wv * sr[i]);
    }
#pragma unroll
    for (int o = 16; o; o >>= 1) acc += __shfl_xor_sync(0xffffffffu, acc, o);
    if (lane == 0) out_f[p] = acc + b5[0];
}

// ---------------- Biot-Savart ----------------
__global__ void k_biot(const float* __restrict__ x, const float* __restrict__ bdry,
                       float* __restrict__ out_alpha, int n, int M) {
    __shared__ float bx[512], by[512], bz[512];
    __shared__ float sgx[512], sgy[512], sgz[512];
    __shared__ float smx[512], smy[512], smz[512];
    int tid = threadIdx.x;
    for (int m = tid; m < M; m += blockDim.x) {
        bx[m] = bdry[m * 3 + 0];
        by[m] = bdry[m * 3 + 1];
        bz[m] = bdry[m * 3 + 2];
    }
    __syncthreads();
    for (int m = tid; m < M; m += blockDim.x) {
        int m2 = (m + 1) == M ? 0 : m + 1;
        sgx[m] = bx[m2] - bx[m];
        sgy[m] = by[m2] - by[m];
        sgz[m] = bz[m2] - bz[m];
        smx[m] = 0.5f * (bx[m2] + bx[m]);
        smy[m] = 0.5f * (by[m2] + by[m]);
        smz[m] = 0.5f * (bz[m2] + bz[m]);
    }
    __syncthreads();
    int p = blockIdx.x * blockDim.x + tid;
    if (p >= n) return;
    float x0 = clip1(x[p * 3 + 0]);
    float x1 = clip1(x[p * 3 + 1]);
    float x2 = clip1(x[p * 3 + 2]);
    float ax = 0.f, ay = 0.f, az = 0.f;
    for (int m = 0; m < M; m++) {
        float dx = x0 - smx[m], dy = x1 - smy[m], dz = x2 - smz[m];
        float cxv = sgy[m] * dz - sgz[m] * dy;
        float cyv = sgz[m] * dx - sgx[m] * dz;
        float czv = sgx[m] * dy - sgy[m] * dx;
        float r2 = dx * dx + dy * dy + dz * dz;
        float inv = rsqrtf(r2);
        float w = inv * inv * inv;
        ax += cxv * w; ay += cyv * w; az += czv * w;
    }
    out_alpha[p * 3 + 0] = INV_4PI_F * ax;
    out_alpha[p * 3 + 1] = INV_4PI_F * ay;
    out_alpha[p * 3 + 2] = INV_4PI_F * az;
}

// ---------------- finish ----------------
__global__ void k_finish(const float* __restrict__ part, const float* __restrict__ alpha,
                         float* __restrict__ out_df, float* __restrict__ out_cur, int n) {
    int p = blockIdx.x * blockDim.x + threadIdx.x;
    if (p >= n) return;
#pragma unroll
    for (int d = 0; d < 3; d++) {
        float s = 0.f;
#pragma unroll
        for (int t = 0; t < 8; t++) s += part[((size_t)t * NMAX + p) * 3 + d];
        out_df[p * 3 + d] = s;
        out_cur[p * 3 + d] = s + alpha[p * 3 + d];
    }
}

// ---------------- launcher ----------------
extern "C" void kernel_launch(void* const* d_in, const int* in_sizes, int n_in,
                              void* d_out, int out_size) {
    const float* x    = (const float*)d_in[0];
    const float* bdry = (const float*)d_in[1];
    const float* B    = (const float*)d_in[2];
    const float* W1   = (const float*)d_in[3];
    const float* b1   = (const float*)d_in[4];
    const float* W2   = (const float*)d_in[5];
    const float* b2   = (const float*)d_in[6];
    const float* W3   = (const float*)d_in[7];
    const float* b3   = (const float*)d_in[8];
    const float* W4   = (const float*)d_in[9];
    const float* b4   = (const float*)d_in[10];
    const float* W5   = (const float*)d_in[11];
    const float* b5   = (const float*)d_in[12];

    int n = in_sizes[0] / 3;
    int M = in_sizes[1] / 3;

    float* out = (float*)d_out;
    float* out_f     = out;
    float* out_cur   = out + (size_t)n;
    float* out_df    = out + (size_t)4 * n;
    float* out_alpha = out + (size_t)7 * n;

    void* pv;
    cudaGetSymbolAddress(&pv, d_W1T);   float* W1T  = (float*)pv;
    cudaGetSymbolAddress(&pv, d_W1P);   float* W1P  = (float*)pv;
    cudaGetSymbolAddress(&pv, d_WmidT); float* WmT  = (float*)pv;
    cudaGetSymbolAddress(&pv, d_WmidR); float* WmR  = (float*)pv;
    cudaGetSymbolAddress(&pv, d_y);     float* yb   = (float*)pv;
    cudaGetSymbolAddress(&pv, d_h);     float* hb   = (float*)pv;
    cudaGetSymbolAddress(&pv, d_s);     float* sb   = (float*)pv;
    cudaGetSymbolAddress(&pv, d_g);     float* gb   = (float*)pv;
    cudaGetSymbolAddress(&pv, d_dfp);   float* dfp  = (float*)pv;

    float *W2T = WmT, *W3T = WmT + 65536, *W4T = WmT + 2 * 65536;
    float *W2R = WmR, *W3R = WmR + 65536, *W4R = WmR + 2 * 65536;

    const size_t HS = (size_t)NMAX * 256;
    float *h1 = hb, *h2 = hb + HS, *h3 = hb + 2 * HS, *h4 = hb + 3 * HS;
    float *s1 = sb, *s2 = sb + HS, *s3 = sb + 2 * HS, *s4 = sb + 3 * HS;
    float *g0 = gb, *g1b = gb + HS;

    const int SMEM = 3 * STG * 4;  // 184320 bytes
    cudaFuncSetAttribute(k_mma<1>, cudaFuncAttributeMaxDynamicSharedMemorySize, SMEM);
    cudaFuncSetAttribute(k_mma<2>, cudaFuncAttributeMaxDynamicSharedMemorySize, SMEM);
    cudaFuncSetAttribute(k_mma<3>, cudaFuncAttributeMaxDynamicSharedMemorySize, SMEM);

    // weight prep
    k_tr<<<(2048 * 256 + 255) / 256, 256>>>(W1, W1T, 2048, 256);
    k_prep_mid<<<(3 * 65536 + 255) / 256, 256>>>(W2, W3, W4, WmT, WmR);
    k_perm<<<(2048 * 256 + 255) / 256, 256>>>(W1, W1P);

    // RFF features
    k_y<<<(n * 256 + 255) / 256, 256>>>(x, B, yb, n);

    dim3 gFwd((n + 127) / 128, 1);
    // forward (layer 4 stores h4 UNROUNDED: feeds f directly)
    k_mma<1><<<gFwd, 256, SMEM>>>(yb, 2048, W1T, 2048, b1, nullptr, h1, s1, 256, 2048, n, 1, nullptr, nullptr, nullptr);
    k_mma<1><<<gFwd, 256, SMEM>>>(h1, 256, W2T, 256, b2, nullptr, h2, s2, 256, 256, n, 1, nullptr, nullptr, nullptr);
    k_mma<1><<<gFwd, 256, SMEM>>>(h2, 256, W3T, 256, b3, nullptr, h3, s3, 256, 256, n, 1, nullptr, nullptr, nullptr);
    k_mma<1><<<gFwd, 256, SMEM>>>(h3, 256, W4T, 256, b4, nullptr, h4, s4, 256, 256, n, 0, nullptr, nullptr, nullptr);

    // head
    k_head<<<(n + 7) / 8, 256>>>(h4, s4, W5, b5, out_f, g0, n);

    // backward through mid layers
    k_mma<2><<<gFwd, 256, SMEM>>>(g0, 256, W4R, 256, nullptr, s3, g1b, nullptr, 256, 256, n, 1, nullptr, nullptr, nullptr);
    k_mma<2><<<gFwd, 256, SMEM>>>(g1b, 256, W3R, 256, nullptr, s2, g0, nullptr, 256, 256, n, 1, nullptr, nullptr, nullptr);
    k_mma<2><<<gFwd, 256, SMEM>>>(g0, 256, W2R, 256, nullptr, s1, g1b, nullptr, 256, 256, n, 1, nullptr, nullptr, nullptr);

    // alpha
    k_biot<<<(n + 255) / 256, 256>>>(x, bdry, out_alpha, n, M);

    // gy GEMM fused with df contraction
    dim3 gGy((n + 127) / 128, 8);
    k_mma<3><<<gGy, 256, SMEM>>>(g1b, 256, W1P, 256, nullptr, nullptr, nullptr, nullptr, 256, 256, n, 0, yb, B, dfp);

    // finish
    k_finish<<<(n + 255) / 256, 256>>>(dfp, out_alpha, out_df, out_cur, n);
}